// round 8
// baseline (speedup 1.0000x reference)
#include <cuda_runtime.h>
#include <math.h>

__device__ unsigned int g_cnt[64];   // zero-init; softmax resets after consuming

// Phase 1: energies[b*2048 + s] = dot(hidden[b,:], enc[s,b,:])
// Known-good 80.4us structure: block = (b, s_chunk), hidden[b] staged in smem,
// 8 independent float4 enc loads in flight per warp, __ldcs evict-first.
// Added: per-batch release arrival (REDG, no return) for fine-grained handoff.
__global__ void __launch_bounds__(256) dot_kernel(
    const float* __restrict__ hidden,   // [64, 1024]
    const float* __restrict__ enc,      // [2048, 64, 1024]
    float* __restrict__ energies)       // [64, 2048]
{
    cudaTriggerProgrammaticLaunchCompletion();   // let softmax CTAs spin up early

    __shared__ float4 sh[256];          // hidden[b] : 4KB

    int b      = blockIdx.x >> 8;       // 0..63
    int schunk = blockIdx.x & 255;      // 0..255

    sh[threadIdx.x] =
        reinterpret_cast<const float4*>(hidden + (size_t)b * 1024)[threadIdx.x];
    __syncthreads();

    int warp = threadIdx.x >> 5;
    int lane = threadIdx.x & 31;
    int s    = schunk * 8 + warp;

    const float4* row = reinterpret_cast<const float4*>(
        enc + ((size_t)s * 64 + b) * 1024);

    float acc = 0.0f;
#pragma unroll
    for (int i = 0; i < 8; i++) {
        float4 e  = __ldcs(&row[lane + i * 32]);
        float4 hv = sh[lane + i * 32];
        acc = fmaf(e.x, hv.x, acc);
        acc = fmaf(e.y, hv.y, acc);
        acc = fmaf(e.z, hv.z, acc);
        acc = fmaf(e.w, hv.w, acc);
    }
#pragma unroll
    for (int o = 16; o; o >>= 1)
        acc += __shfl_xor_sync(0xffffffffu, acc, o);

    if (lane == 0) {
        energies[b * 2048 + s] = acc;
        // release-arrival: orders the store above, no return value -> no stall
        asm volatile("red.release.gpu.global.add.u32 [%0], %1;"
                     :: "l"(&g_cnt[b]), "r"(1u) : "memory");
    }
}

// Phase 2: warp-per-row softmax. Spins on its batch counter (acquire), so it
// starts as soon as ITS batch is done, not when the whole dot grid is done.
__global__ void __launch_bounds__(32) softmax_kernel(float* __restrict__ out)
{
    int b    = blockIdx.x;
    int lane = threadIdx.x;
    float* p = out + (size_t)b * 2048;

    if (lane == 0) {
        unsigned int v;
        do {
            asm volatile("ld.acquire.gpu.global.u32 %0, [%1];"
                         : "=r"(v) : "l"(&g_cnt[b]) : "memory");
        } while (v < 2048u);
    }
    __syncwarp();

    const float4* pv = reinterpret_cast<const float4*>(p);
    float4 v[16];
#pragma unroll
    for (int i = 0; i < 16; i++)
        v[i] = __ldcg(&pv[lane + i * 32]);

    float m = -INFINITY;
#pragma unroll
    for (int i = 0; i < 16; i++)
        m = fmaxf(m, fmaxf(fmaxf(v[i].x, v[i].y), fmaxf(v[i].z, v[i].w)));
#pragma unroll
    for (int o = 16; o; o >>= 1)
        m = fmaxf(m, __shfl_xor_sync(0xffffffffu, m, o));

    float s = 0.0f;
#pragma unroll
    for (int i = 0; i < 16; i++) {
        v[i].x = __expf(v[i].x - m);
        v[i].y = __expf(v[i].y - m);
        v[i].z = __expf(v[i].z - m);
        v[i].w = __expf(v[i].w - m);
        s += (v[i].x + v[i].y) + (v[i].z + v[i].w);
    }
#pragma unroll
    for (int o = 16; o; o >>= 1)
        s += __shfl_xor_sync(0xffffffffu, s, o);
    float inv = 1.0f / s;

    float4* pw = reinterpret_cast<float4*>(p);
#pragma unroll
    for (int i = 0; i < 16; i++) {
        float4 w = v[i];
        w.x *= inv; w.y *= inv; w.z *= inv; w.w *= inv;
        pw[lane + i * 32] = w;
    }

    // reset for next graph replay (next dot launch is stream-ordered after us)
    if (lane == 0) g_cnt[b] = 0;
}

extern "C" void kernel_launch(void* const* d_in, const int* in_sizes, int n_in,
                              void* d_out, int out_size)
{
    const float* hidden = (const float*)d_in[0];   // [1, 64, 1024]
    const float* enc    = (const float*)d_in[1];   // [2048, 64, 1024]
    float* out          = (float*)d_out;           // [64, 1, 2048]

    dot_kernel<<<16384, 256>>>(hidden, enc, out);

    // PDL: softmax CTAs launch once dot CTAs have triggered; per-batch spin
    // does the fine-grained ordering.
    cudaLaunchConfig_t cfg = {};
    cfg.gridDim  = dim3(64, 1, 1);
    cfg.blockDim = dim3(32, 1, 1);
    cfg.dynamicSmemBytes = 0;
    cfg.stream = 0;
    cudaLaunchAttribute attrs[1];
    attrs[0].id = cudaLaunchAttributeProgrammaticStreamSerialization;
    attrs[0].val.programmaticStreamSerializationAllowed = 1;
    cfg.attrs = attrs;
    cfg.numAttrs = 1;
    cudaLaunchKernelEx(&cfg, softmax_kernel, out);
}

// round 9
// speedup vs baseline: 2.0656x; 2.0656x over previous
#include <cuda_runtime.h>
#include <math.h>

// Phase 1: energies[b*2048 + s] = dot(hidden[b,:], enc[s,b,:])
// EXACT R7 structure (80.4us known-good): block = (b, s_chunk), hidden[b]
// staged in smem, 8 independent float4 enc loads per warp, __ldcs stream.
// NO atomics, NO fences (every variant with them regressed ~2x).
// Added only: PDL trigger at entry so the softmax kernel can launch early.
__global__ void __launch_bounds__(256) dot_kernel(
    const float* __restrict__ hidden,   // [64, 1024]
    const float* __restrict__ enc,      // [2048, 64, 1024]
    float* __restrict__ energies)       // [64, 2048]
{
    cudaTriggerProgrammaticLaunchCompletion();

    __shared__ float4 sh[256];          // hidden[b] : 4KB

    int b      = blockIdx.x >> 8;       // 0..63
    int schunk = blockIdx.x & 255;      // 0..255

    sh[threadIdx.x] =
        reinterpret_cast<const float4*>(hidden + (size_t)b * 1024)[threadIdx.x];
    __syncthreads();

    int warp = threadIdx.x >> 5;
    int lane = threadIdx.x & 31;
    int s    = schunk * 8 + warp;

    const float4* row = reinterpret_cast<const float4*>(
        enc + ((size_t)s * 64 + b) * 1024);

    float acc = 0.0f;
#pragma unroll
    for (int i = 0; i < 8; i++) {
        float4 e  = __ldcs(&row[lane + i * 32]);
        float4 hv = sh[lane + i * 32];
        acc = fmaf(e.x, hv.x, acc);
        acc = fmaf(e.y, hv.y, acc);
        acc = fmaf(e.z, hv.z, acc);
        acc = fmaf(e.w, hv.w, acc);
    }
#pragma unroll
    for (int o = 16; o; o >>= 1)
        acc += __shfl_xor_sync(0xffffffffu, acc, o);

    if (lane == 0)
        energies[b * 2048 + s] = acc;
}

// Phase 2: softmax, 4 warps per row (64 CTAs x 128 thr). Short serial chain:
// 4 float4 loads/lane (MLP=4 x 4 warps), 16 exp/lane, 2 smem combines.
__global__ void __launch_bounds__(128) softmax_kernel(float* __restrict__ out)
{
    __shared__ float red[8];   // [0..3]=per-warp max, [4..7]=per-warp sum

    int b    = blockIdx.x;
    int tid  = threadIdx.x;
    int warp = tid >> 5;
    int lane = tid & 31;
    float* p = out + (size_t)b * 2048;

    cudaGridDependencySynchronize();   // full ordering vs dot grid

    // warp w owns values [w*512, (w+1)*512): 4 float4 per lane
    const float4* pv = reinterpret_cast<const float4*>(p) + warp * 128;
    float4 v[4];
#pragma unroll
    for (int i = 0; i < 4; i++)
        v[i] = __ldcg(&pv[lane + i * 32]);

    // --- block max ---
    float m = -INFINITY;
#pragma unroll
    for (int i = 0; i < 4; i++)
        m = fmaxf(m, fmaxf(fmaxf(v[i].x, v[i].y), fmaxf(v[i].z, v[i].w)));
#pragma unroll
    for (int o = 16; o; o >>= 1)
        m = fmaxf(m, __shfl_xor_sync(0xffffffffu, m, o));
    if (lane == 0) red[warp] = m;
    __syncthreads();
    m = fmaxf(fmaxf(red[0], red[1]), fmaxf(red[2], red[3]));

    // --- exp + block sum ---
    float s = 0.0f;
#pragma unroll
    for (int i = 0; i < 4; i++) {
        v[i].x = __expf(v[i].x - m);
        v[i].y = __expf(v[i].y - m);
        v[i].z = __expf(v[i].z - m);
        v[i].w = __expf(v[i].w - m);
        s += (v[i].x + v[i].y) + (v[i].z + v[i].w);
    }
#pragma unroll
    for (int o = 16; o; o >>= 1)
        s += __shfl_xor_sync(0xffffffffu, s, o);
    if (lane == 0) red[4 + warp] = s;
    __syncthreads();
    float inv = 1.0f / (((red[4] + red[5]) + (red[6] + red[7])));

    float4* pw = reinterpret_cast<float4*>(p) + warp * 128;
#pragma unroll
    for (int i = 0; i < 4; i++) {
        float4 w = v[i];
        w.x *= inv; w.y *= inv; w.z *= inv; w.w *= inv;
        pw[lane + i * 32] = w;
    }
}

extern "C" void kernel_launch(void* const* d_in, const int* in_sizes, int n_in,
                              void* d_out, int out_size)
{
    const float* hidden = (const float*)d_in[0];   // [1, 64, 1024]
    const float* enc    = (const float*)d_in[1];   // [2048, 64, 1024]
    float* out          = (float*)d_out;           // [64, 1, 2048]

    dot_kernel<<<16384, 256>>>(hidden, enc, out);

    cudaLaunchConfig_t cfg = {};
    cfg.gridDim  = dim3(64, 1, 1);
    cfg.blockDim = dim3(128, 1, 1);
    cfg.dynamicSmemBytes = 0;
    cfg.stream = 0;
    cudaLaunchAttribute attrs[1];
    attrs[0].id = cudaLaunchAttributeProgrammaticStreamSerialization;
    attrs[0].val.programmaticStreamSerializationAllowed = 1;
    cfg.attrs = attrs;
    cfg.numAttrs = 1;
    cudaLaunchKernelEx(&cfg, softmax_kernel, out);
}